// round 7
// baseline (speedup 1.0000x reference)
#include <cuda_runtime.h>
#include <cstdint>

#define N_NODES 50000
#define N_EDGES 800000
#define D 128
#define NCLS 64
#define SCAN_B 1024
#define SCAN_NBLK ((N_NODES + SCAN_B - 1) / SCAN_B)   // 49

// ---------------------------------------------------------------------------
// Device-global scratch
// ---------------------------------------------------------------------------
__device__ __align__(16) float g_y[N_NODES * D];
__device__ __align__(16) float g_h[N_NODES * D];
__device__ int g_row_ptr[N_NODES + 1];
__device__ int g_cursor[N_NODES];
__device__ int g_cnt[N_NODES];
__device__ int g_col[N_EDGES];
__device__ int g_partials[SCAN_NBLK];

// ---------------------------------------------------------------------------
// CSR: zero -> hist(x4 MLP) -> scan_block -> scan_add(fused partials) -> fill
// ---------------------------------------------------------------------------
__global__ void zero_cnt_kernel(int* __restrict__ cnt) {
    int i = blockIdx.x * blockDim.x + threadIdx.x;
    if (i < N_NODES) cnt[i] = 0;
}

__global__ void __launch_bounds__(256) hist_kernel(
    const int* __restrict__ dst, int* __restrict__ cnt)
{
    int base = (blockIdx.x * blockDim.x + threadIdx.x) * 4;
    if (base + 3 < N_EDGES) {
        int4 d4 = *reinterpret_cast<const int4*>(dst + base);
        atomicAdd(cnt + d4.x, 1);
        atomicAdd(cnt + d4.y, 1);
        atomicAdd(cnt + d4.z, 1);
        atomicAdd(cnt + d4.w, 1);
    } else {
        for (int e = base; e < N_EDGES; e++) atomicAdd(cnt + dst[e], 1);
    }
}

__global__ void __launch_bounds__(SCAN_B) scan_block_kernel(
    const int* __restrict__ cnt, int* __restrict__ row_ptr, int* __restrict__ partials)
{
    __shared__ int wsum[32];
    int i = blockIdx.x * SCAN_B + threadIdx.x;
    int lane = threadIdx.x & 31;
    int wid  = threadIdx.x >> 5;

    int v = (i < N_NODES) ? cnt[i] : 0;
    int x = v;
    #pragma unroll
    for (int off = 1; off < 32; off <<= 1) {
        int t = __shfl_up_sync(0xffffffffu, x, off);
        if (lane >= off) x += t;
    }
    if (lane == 31) wsum[wid] = x;
    __syncthreads();
    if (wid == 0) {
        int w = wsum[lane];
        #pragma unroll
        for (int off = 1; off < 32; off <<= 1) {
            int t = __shfl_up_sync(0xffffffffu, w, off);
            if (lane >= off) w += t;
        }
        wsum[lane] = w;
    }
    __syncthreads();

    int excl = x - v + (wid ? wsum[wid - 1] : 0);
    if (i < N_NODES) row_ptr[i] = excl;
    if (threadIdx.x == SCAN_B - 1) partials[blockIdx.x] = excl + v;
}

__global__ void __launch_bounds__(SCAN_B) scan_add_kernel(
    int* __restrict__ row_ptr, int* __restrict__ cursor, const int* __restrict__ partials)
{
    __shared__ int sp[SCAN_NBLK];
    if (threadIdx.x < SCAN_NBLK) sp[threadIdx.x] = partials[threadIdx.x];
    __syncthreads();
    if (threadIdx.x == 0) {
        int run = 0;
        #pragma unroll
        for (int k = 0; k < SCAN_NBLK; k++) { int t = sp[k]; sp[k] = run; run += t; }
    }
    __syncthreads();

    int i = blockIdx.x * SCAN_B + threadIdx.x;
    if (i < N_NODES) {
        int r = row_ptr[i] + sp[blockIdx.x];
        row_ptr[i] = r;
        cursor[i]  = r;
    }
    if (i == 0) row_ptr[N_NODES] = N_EDGES;
}

__global__ void __launch_bounds__(256) fill_kernel(
    const int* __restrict__ src, const int* __restrict__ dst,
    int* __restrict__ cursor, int* __restrict__ col)
{
    int base = (blockIdx.x * blockDim.x + threadIdx.x) * 4;
    if (base + 3 < N_EDGES) {
        int4 d4 = *reinterpret_cast<const int4*>(dst + base);
        int4 s4 = *reinterpret_cast<const int4*>(src + base);
        int p0 = atomicAdd(cursor + d4.x, 1);
        int p1 = atomicAdd(cursor + d4.y, 1);
        int p2 = atomicAdd(cursor + d4.z, 1);
        int p3 = atomicAdd(cursor + d4.w, 1);
        col[p0] = s4.x; col[p1] = s4.y; col[p2] = s4.z; col[p3] = s4.w;
    } else {
        for (int e = base; e < N_EDGES; e++) {
            int pos = atomicAdd(cursor + dst[e], 1);
            col[pos] = src[e];
        }
    }
}

// ---------------------------------------------------------------------------
// f32x2 GEMM (2 fp32 FMAs / instruction, full fp32 precision)
// y[n,j] = sum_k A[n,k] * W[j,k].  BM=64 rows, 256 threads.
// NOUT=128: TX=16,TY=16,RPT=4.  NOUT=64: TX=8,TY=32,RPT=2.
// ---------------------------------------------------------------------------
template <int NOUT>
__global__ void __launch_bounds__(256) gemm_kernel(
    const float* __restrict__ A, const float* __restrict__ W, float* __restrict__ y)
{
    constexpr int BM  = 64;
    constexpr int TX  = NOUT / 8;
    constexpr int TY  = 256 / TX;
    constexpr int RPT = BM / TY;
    constexpr int SXS = D + 4;
    constexpr int SWS = NOUT + 4;

    extern __shared__ float smem[];
    float* sX = smem;
    float* sW = smem + BM * SXS;

    const int tid  = threadIdx.x;
    const int row0 = blockIdx.x * BM;

    #pragma unroll
    for (int i = tid; i < BM * (D / 4); i += 256) {
        int r  = i >> 5;
        int c4 = i & 31;
        int gr = row0 + r;
        float4 v = make_float4(0.f, 0.f, 0.f, 0.f);
        if (gr < N_NODES) v = reinterpret_cast<const float4*>(A + (size_t)gr * D)[c4];
        reinterpret_cast<float4*>(sX + r * SXS)[c4] = v;
    }
    #pragma unroll
    for (int i = tid; i < NOUT * (D / 4); i += 256) {
        int n  = i >> 5;
        int k4 = i & 31;
        float4 v = reinterpret_cast<const float4*>(W)[i];
        sW[(k4 * 4 + 0) * SWS + n] = v.x;
        sW[(k4 * 4 + 1) * SWS + n] = v.y;
        sW[(k4 * 4 + 2) * SWS + n] = v.z;
        sW[(k4 * 4 + 3) * SWS + n] = v.w;
    }
    __syncthreads();

    const int tx = tid % TX;
    const int ty = tid / TX;
    const int cbase = tx * 8;
    const int rbase = ty * RPT;

    unsigned long long acc[RPT][4];
    #pragma unroll
    for (int r = 0; r < RPT; r++)
        #pragma unroll
        for (int c = 0; c < 4; c++) acc[r][c] = 0ULL;

    #pragma unroll 4
    for (int k = 0; k < D; k++) {
        const ulonglong2* bp = reinterpret_cast<const ulonglong2*>(sW + k * SWS + cbase);
        ulonglong2 bA = bp[0];
        ulonglong2 bB = bp[1];
        #pragma unroll
        for (int r = 0; r < RPT; r++) {
            float a = sX[(rbase + r) * SXS + k];
            unsigned long long a2;
            asm("mov.b64 %0, {%1, %1};" : "=l"(a2) : "f"(a));
            asm("fma.rn.f32x2 %0, %1, %2, %0;" : "+l"(acc[r][0]) : "l"(a2), "l"(bA.x));
            asm("fma.rn.f32x2 %0, %1, %2, %0;" : "+l"(acc[r][1]) : "l"(a2), "l"(bA.y));
            asm("fma.rn.f32x2 %0, %1, %2, %0;" : "+l"(acc[r][2]) : "l"(a2), "l"(bB.x));
            asm("fma.rn.f32x2 %0, %1, %2, %0;" : "+l"(acc[r][3]) : "l"(a2), "l"(bB.y));
        }
    }

    #pragma unroll
    for (int r = 0; r < RPT; r++) {
        int row = row0 + rbase + r;
        if (row >= N_NODES) continue;
        float o[8];
        #pragma unroll
        for (int c = 0; c < 4; c++)
            asm("mov.b64 {%0, %1}, %2;" : "=f"(o[2*c]), "=f"(o[2*c+1]) : "l"(acc[r][c]));
        float4* dst4 = reinterpret_cast<float4*>(y + (size_t)row * NOUT + cbase);
        dst4[0] = make_float4(o[0], o[1], o[2], o[3]);
        dst4[1] = make_float4(o[4], o[5], o[6], o[7]);
    }
}

// ---------------------------------------------------------------------------
// CSR aggregation + bias + relu. One warp per node, 8 gathers in flight.
// ---------------------------------------------------------------------------
__global__ void __launch_bounds__(256) aggregate128_kernel(
    const float* __restrict__ y, const int* __restrict__ row_ptr,
    const int* __restrict__ col, const float* __restrict__ bias,
    float* __restrict__ out)
{
    int node = (blockIdx.x * blockDim.x + threadIdx.x) >> 5;
    int lane = threadIdx.x & 31;
    if (node >= N_NODES) return;

    int beg = __ldg(row_ptr + node);
    int end = __ldg(row_ptr + node + 1);

    const float4* base = reinterpret_cast<const float4*>(y);
    float4 a0 = base[(size_t)node * 32 + lane];
    float4 a1 = make_float4(0.f, 0.f, 0.f, 0.f);

    int j = beg;
    for (; j + 7 < end; j += 8) {
        int c[8];
        #pragma unroll
        for (int u = 0; u < 8; u++) c[u] = __ldg(col + j + u);
        float4 v[8];
        #pragma unroll
        for (int u = 0; u < 8; u++) v[u] = base[(size_t)c[u] * 32 + lane];
        #pragma unroll
        for (int u = 0; u < 8; u += 2) {
            a0.x += v[u].x;   a0.y += v[u].y;   a0.z += v[u].z;   a0.w += v[u].w;
            a1.x += v[u+1].x; a1.y += v[u+1].y; a1.z += v[u+1].z; a1.w += v[u+1].w;
        }
    }
    for (; j < end; j++) {
        int c0 = __ldg(col + j);
        float4 v0 = base[(size_t)c0 * 32 + lane];
        a0.x += v0.x; a0.y += v0.y; a0.z += v0.z; a0.w += v0.w;
    }
    a0.x += a1.x; a0.y += a1.y; a0.z += a1.z; a0.w += a1.w;

    float4 b = reinterpret_cast<const float4*>(bias)[lane];
    float4 o;
    o.x = fmaxf(a0.x + b.x, 0.f);
    o.y = fmaxf(a0.y + b.y, 0.f);
    o.z = fmaxf(a0.z + b.z, 0.f);
    o.w = fmaxf(a0.w + b.w, 0.f);
    reinterpret_cast<float4*>(out)[(size_t)node * 32 + lane] = o;
}

__global__ void __launch_bounds__(256) aggregate64_kernel(
    const float* __restrict__ y, const int* __restrict__ row_ptr,
    const int* __restrict__ col, const float* __restrict__ bias,
    float* __restrict__ out)
{
    int node = (blockIdx.x * blockDim.x + threadIdx.x) >> 5;
    int lane = threadIdx.x & 31;
    if (node >= N_NODES) return;

    int beg = __ldg(row_ptr + node);
    int end = __ldg(row_ptr + node + 1);

    const float2* base = reinterpret_cast<const float2*>(y);
    float2 a0 = base[(size_t)node * 32 + lane];
    float2 a1 = make_float2(0.f, 0.f);

    int j = beg;
    for (; j + 7 < end; j += 8) {
        int c[8];
        #pragma unroll
        for (int u = 0; u < 8; u++) c[u] = __ldg(col + j + u);
        float2 v[8];
        #pragma unroll
        for (int u = 0; u < 8; u++) v[u] = base[(size_t)c[u] * 32 + lane];
        #pragma unroll
        for (int u = 0; u < 8; u += 2) {
            a0.x += v[u].x;   a0.y += v[u].y;
            a1.x += v[u+1].x; a1.y += v[u+1].y;
        }
    }
    for (; j < end; j++) {
        int c0 = __ldg(col + j);
        float2 v0 = base[(size_t)c0 * 32 + lane];
        a0.x += v0.x; a0.y += v0.y;
    }
    a0.x += a1.x; a0.y += a1.y;

    float2 b = reinterpret_cast<const float2*>(bias)[lane];
    float2 o;
    o.x = fmaxf(a0.x + b.x, 0.f);
    o.y = fmaxf(a0.y + b.y, 0.f);
    reinterpret_cast<float2*>(out)[(size_t)node * 32 + lane] = o;
}

// ---------------------------------------------------------------------------
// Launch: single stream, R3 structure. 11 kernels total.
// ---------------------------------------------------------------------------
extern "C" void kernel_launch(void* const* d_in, const int* in_sizes, int n_in,
                              void* d_out, int out_size)
{
    const float* in_feat = (const float*)d_in[0];
    const float* W1 = (const float*)d_in[1];
    const float* b1 = (const float*)d_in[2];
    const float* W2 = (const float*)d_in[3];
    const float* b2 = (const float*)d_in[4];
    const float* W3 = (const float*)d_in[5];
    const float* b3 = (const float*)d_in[6];
    const int*   src = (const int*)d_in[7];
    const int*   dst = (const int*)d_in[8];
    float* out = (float*)d_out;

    float *y, *h;
    int *row_ptr, *cursor, *cnt, *col, *partials;
    cudaGetSymbolAddress((void**)&y, g_y);
    cudaGetSymbolAddress((void**)&h, g_h);
    cudaGetSymbolAddress((void**)&row_ptr, g_row_ptr);
    cudaGetSymbolAddress((void**)&cursor, g_cursor);
    cudaGetSymbolAddress((void**)&cnt, g_cnt);
    cudaGetSymbolAddress((void**)&col, g_col);
    cudaGetSymbolAddress((void**)&partials, g_partials);

    const int smem128 = (64 * (D + 4) + D * (128 + 4)) * (int)sizeof(float);
    const int smem64  = (64 * (D + 4) + D * (64 + 4))  * (int)sizeof(float);
    cudaFuncSetAttribute(gemm_kernel<128>,
                         cudaFuncAttributeMaxDynamicSharedMemorySize, smem128);
    cudaFuncSetAttribute(gemm_kernel<64>,
                         cudaFuncAttributeMaxDynamicSharedMemorySize, smem64);

    const int node_blocks  = (N_NODES + 255) / 256;
    const int edge4_blocks = (N_EDGES / 4 + 255) / 256;
    const int gemm_blocks  = (N_NODES + 63) / 64;
    const int agg_blocks   = (N_NODES * 32 + 255) / 256;

    // ---- CSR build ----
    zero_cnt_kernel<<<node_blocks, 256>>>(cnt);
    hist_kernel<<<edge4_blocks, 256>>>(dst, cnt);
    scan_block_kernel<<<SCAN_NBLK, SCAN_B>>>(cnt, row_ptr, partials);
    scan_add_kernel<<<SCAN_NBLK, SCAN_B>>>(row_ptr, cursor, partials);
    fill_kernel<<<edge4_blocks, 256>>>(src, dst, cursor, col);

    // ---- Layer 1: y = in_feat @ W1 ; h = relu(y + Ay + b1) ----
    gemm_kernel<128><<<gemm_blocks, 256, smem128>>>(in_feat, W1, y);
    aggregate128_kernel<<<agg_blocks, 256>>>(y, row_ptr, col, b1, h);

    // ---- Layer 2: y = h @ W2 ; h = relu(y + Ay + b2) ----
    gemm_kernel<128><<<gemm_blocks, 256, smem128>>>(h, W2, y);
    aggregate128_kernel<<<agg_blocks, 256>>>(y, row_ptr, col, b2, h);

    // ---- Layer 3: y = h @ W3 (64) ; out = relu(y + Ay + b3) ----
    gemm_kernel<64><<<gemm_blocks, 256, smem64>>>(h, W3, y);
    aggregate64_kernel<<<agg_blocks, 256>>>(y, row_ptr, col, b3, out);
}

// round 8
// speedup vs baseline: 1.2384x; 1.2384x over previous
#include <cuda_runtime.h>
#include <cstdint>

#define N_NODES 50000
#define N_EDGES 800000
#define D 128
#define NCLS 64
#define SCAN_B 1024
#define SCAN_NBLK ((N_NODES + SCAN_B - 1) / SCAN_B)   // 49

// ---------------------------------------------------------------------------
// Device-global scratch
// ---------------------------------------------------------------------------
__device__ __align__(16) float g_y[N_NODES * D];
__device__ __align__(16) float g_h[N_NODES * D];
__device__ int g_row_ptr[N_NODES + 1];
__device__ int g_cursor[N_NODES];
__device__ int g_cnt[N_NODES];
__device__ int g_col[N_EDGES];
__device__ int g_partials[SCAN_NBLK];

// ---------------------------------------------------------------------------
// CSR: memset(cnt) -> hist(x4 MLP) -> scan_block -> scan_partials -> scan_add -> fill
// ---------------------------------------------------------------------------
__global__ void __launch_bounds__(256) hist_kernel(
    const int* __restrict__ dst, int* __restrict__ cnt)
{
    int base = (blockIdx.x * blockDim.x + threadIdx.x) * 4;
    if (base + 3 < N_EDGES) {
        int4 d4 = *reinterpret_cast<const int4*>(dst + base);
        atomicAdd(cnt + d4.x, 1);
        atomicAdd(cnt + d4.y, 1);
        atomicAdd(cnt + d4.z, 1);
        atomicAdd(cnt + d4.w, 1);
    } else {
        for (int e = base; e < N_EDGES; e++) atomicAdd(cnt + dst[e], 1);
    }
}

__global__ void __launch_bounds__(SCAN_B) scan_block_kernel(
    const int* __restrict__ cnt, int* __restrict__ row_ptr, int* __restrict__ partials)
{
    __shared__ int wsum[32];
    int i = blockIdx.x * SCAN_B + threadIdx.x;
    int lane = threadIdx.x & 31;
    int wid  = threadIdx.x >> 5;

    int v = (i < N_NODES) ? cnt[i] : 0;
    int x = v;
    #pragma unroll
    for (int off = 1; off < 32; off <<= 1) {
        int t = __shfl_up_sync(0xffffffffu, x, off);
        if (lane >= off) x += t;
    }
    if (lane == 31) wsum[wid] = x;
    __syncthreads();
    if (wid == 0) {
        int w = wsum[lane];
        #pragma unroll
        for (int off = 1; off < 32; off <<= 1) {
            int t = __shfl_up_sync(0xffffffffu, w, off);
            if (lane >= off) w += t;
        }
        wsum[lane] = w;
    }
    __syncthreads();

    int excl = x - v + (wid ? wsum[wid - 1] : 0);
    if (i < N_NODES) row_ptr[i] = excl;
    if (threadIdx.x == SCAN_B - 1) partials[blockIdx.x] = excl + v;
}

__global__ void __launch_bounds__(SCAN_B) scan_add_kernel(
    int* __restrict__ row_ptr, int* __restrict__ cursor, const int* __restrict__ partials)
{
    __shared__ int sp[SCAN_NBLK];
    if (threadIdx.x < SCAN_NBLK) sp[threadIdx.x] = partials[threadIdx.x];
    __syncthreads();
    if (threadIdx.x == 0) {
        int run = 0;
        #pragma unroll
        for (int k = 0; k < SCAN_NBLK; k++) { int t = sp[k]; sp[k] = run; run += t; }
    }
    __syncthreads();

    int i = blockIdx.x * SCAN_B + threadIdx.x;
    if (i < N_NODES) {
        int r = row_ptr[i] + sp[blockIdx.x];
        row_ptr[i] = r;
        cursor[i]  = r;
    }
    if (i == 0) row_ptr[N_NODES] = N_EDGES;
}

__global__ void __launch_bounds__(256) fill_kernel(
    const int* __restrict__ src, const int* __restrict__ dst,
    int* __restrict__ cursor, int* __restrict__ col)
{
    int base = (blockIdx.x * blockDim.x + threadIdx.x) * 4;
    if (base + 3 < N_EDGES) {
        int4 d4 = *reinterpret_cast<const int4*>(dst + base);
        int4 s4 = *reinterpret_cast<const int4*>(src + base);
        int p0 = atomicAdd(cursor + d4.x, 1);
        int p1 = atomicAdd(cursor + d4.y, 1);
        int p2 = atomicAdd(cursor + d4.z, 1);
        int p3 = atomicAdd(cursor + d4.w, 1);
        col[p0] = s4.x; col[p1] = s4.y; col[p2] = s4.z; col[p3] = s4.w;
    } else {
        for (int e = base; e < N_EDGES; e++) {
            int pos = atomicAdd(cursor + dst[e], 1);
            col[pos] = src[e];
        }
    }
}

// ---------------------------------------------------------------------------
// GEMM via packed fma.rn.f32x2 (2 fp32 FMAs per instruction, full precision)
// y[n,j] = sum_k A[n,k] * W[j,k].  BM=64 rows/block, 128 threads.
// NOUT=128: 16x8 threads, each 8 rows x 8 cols.  NOUT=64: 8x16, 4 rows x 8 cols.
// (This is the R3 configuration that measured fastest.)
// ---------------------------------------------------------------------------
template <int NOUT>
__global__ void __launch_bounds__(128) gemm_kernel(
    const float* __restrict__ A, const float* __restrict__ W, float* __restrict__ y)
{
    constexpr int BM  = 64;
    constexpr int TX  = NOUT / 8;        // 16 or 8
    constexpr int TY  = 128 / TX;        // 8 or 16
    constexpr int RPT = BM / TY;         // 8 or 4
    constexpr int SXS = D + 4;           // 132
    constexpr int SWS = NOUT + 4;        // 132 or 68

    extern __shared__ float smem[];
    float* sX = smem;                    // [BM][SXS]
    float* sW = smem + BM * SXS;         // [D][SWS]  (W transposed)

    const int tid  = threadIdx.x;
    const int row0 = blockIdx.x * BM;

    #pragma unroll
    for (int i = tid; i < BM * (D / 4); i += 128) {
        int r  = i >> 5;
        int c4 = i & 31;
        int gr = row0 + r;
        float4 v = make_float4(0.f, 0.f, 0.f, 0.f);
        if (gr < N_NODES) v = reinterpret_cast<const float4*>(A + (size_t)gr * D)[c4];
        reinterpret_cast<float4*>(sX + r * SXS)[c4] = v;
    }
    #pragma unroll
    for (int i = tid; i < NOUT * (D / 4); i += 128) {
        int n  = i >> 5;
        int k4 = i & 31;
        float4 v = reinterpret_cast<const float4*>(W)[i];
        sW[(k4 * 4 + 0) * SWS + n] = v.x;
        sW[(k4 * 4 + 1) * SWS + n] = v.y;
        sW[(k4 * 4 + 2) * SWS + n] = v.z;
        sW[(k4 * 4 + 3) * SWS + n] = v.w;
    }
    __syncthreads();

    const int tx = tid % TX;
    const int ty = tid / TX;
    const int cbase = tx * 8;
    const int rbase = ty * RPT;

    unsigned long long acc[RPT][4];
    #pragma unroll
    for (int r = 0; r < RPT; r++)
        #pragma unroll
        for (int c = 0; c < 4; c++) acc[r][c] = 0ULL;

    #pragma unroll 4
    for (int k = 0; k < D; k++) {
        const ulonglong2* bp = reinterpret_cast<const ulonglong2*>(sW + k * SWS + cbase);
        ulonglong2 bA = bp[0];
        ulonglong2 bB = bp[1];
        #pragma unroll
        for (int r = 0; r < RPT; r++) {
            float a = sX[(rbase + r) * SXS + k];
            unsigned long long a2;
            asm("mov.b64 %0, {%1, %1};" : "=l"(a2) : "f"(a));
            asm("fma.rn.f32x2 %0, %1, %2, %0;" : "+l"(acc[r][0]) : "l"(a2), "l"(bA.x));
            asm("fma.rn.f32x2 %0, %1, %2, %0;" : "+l"(acc[r][1]) : "l"(a2), "l"(bA.y));
            asm("fma.rn.f32x2 %0, %1, %2, %0;" : "+l"(acc[r][2]) : "l"(a2), "l"(bB.x));
            asm("fma.rn.f32x2 %0, %1, %2, %0;" : "+l"(acc[r][3]) : "l"(a2), "l"(bB.y));
        }
    }

    #pragma unroll
    for (int r = 0; r < RPT; r++) {
        int row = row0 + rbase + r;
        if (row >= N_NODES) continue;
        float o[8];
        #pragma unroll
        for (int c = 0; c < 4; c++)
            asm("mov.b64 {%0, %1}, %2;" : "=f"(o[2*c]), "=f"(o[2*c+1]) : "l"(acc[r][c]));
        float4* dst4 = reinterpret_cast<float4*>(y + (size_t)row * NOUT + cbase);
        dst4[0] = make_float4(o[0], o[1], o[2], o[3]);
        dst4[1] = make_float4(o[4], o[5], o[6], o[7]);
    }
}

// ---------------------------------------------------------------------------
// CSR aggregation + bias + relu. One warp per node, 4 gathers in flight (R3).
// ---------------------------------------------------------------------------
__global__ void __launch_bounds__(256) aggregate128_kernel(
    const float* __restrict__ y, const int* __restrict__ row_ptr,
    const int* __restrict__ col, const float* __restrict__ bias,
    float* __restrict__ out)
{
    int node = (blockIdx.x * blockDim.x + threadIdx.x) >> 5;
    int lane = threadIdx.x & 31;
    if (node >= N_NODES) return;

    int beg = __ldg(row_ptr + node);
    int end = __ldg(row_ptr + node + 1);

    const float4* base = reinterpret_cast<const float4*>(y);
    float4 acc = base[(size_t)node * 32 + lane];
    float4 acc2 = make_float4(0.f, 0.f, 0.f, 0.f);

    int j = beg;
    for (; j + 3 < end; j += 4) {
        int c0 = __ldg(col + j);
        int c1 = __ldg(col + j + 1);
        int c2 = __ldg(col + j + 2);
        int c3 = __ldg(col + j + 3);
        float4 v0 = base[(size_t)c0 * 32 + lane];
        float4 v1 = base[(size_t)c1 * 32 + lane];
        float4 v2 = base[(size_t)c2 * 32 + lane];
        float4 v3 = base[(size_t)c3 * 32 + lane];
        acc.x  += v0.x; acc.y  += v0.y; acc.z  += v0.z; acc.w  += v0.w;
        acc2.x += v1.x; acc2.y += v1.y; acc2.z += v1.z; acc2.w += v1.w;
        acc.x  += v2.x; acc.y  += v2.y; acc.z  += v2.z; acc.w  += v2.w;
        acc2.x += v3.x; acc2.y += v3.y; acc2.z += v3.z; acc2.w += v3.w;
    }
    for (; j < end; j++) {
        int c0 = __ldg(col + j);
        float4 v0 = base[(size_t)c0 * 32 + lane];
        acc.x += v0.x; acc.y += v0.y; acc.z += v0.z; acc.w += v0.w;
    }
    acc.x += acc2.x; acc.y += acc2.y; acc.z += acc2.z; acc.w += acc2.w;

    float4 b = reinterpret_cast<const float4*>(bias)[lane];
    float4 o;
    o.x = fmaxf(acc.x + b.x, 0.f);
    o.y = fmaxf(acc.y + b.y, 0.f);
    o.z = fmaxf(acc.z + b.z, 0.f);
    o.w = fmaxf(acc.w + b.w, 0.f);
    reinterpret_cast<float4*>(out)[(size_t)node * 32 + lane] = o;
}

__global__ void __launch_bounds__(256) aggregate64_kernel(
    const float* __restrict__ y, const int* __restrict__ row_ptr,
    const int* __restrict__ col, const float* __restrict__ bias,
    float* __restrict__ out)
{
    int node = (blockIdx.x * blockDim.x + threadIdx.x) >> 5;
    int lane = threadIdx.x & 31;
    if (node >= N_NODES) return;

    int beg = __ldg(row_ptr + node);
    int end = __ldg(row_ptr + node + 1);

    const float2* base = reinterpret_cast<const float2*>(y);
    float2 acc = base[(size_t)node * 32 + lane];
    float2 acc2 = make_float2(0.f, 0.f);

    int j = beg;
    for (; j + 3 < end; j += 4) {
        int c0 = __ldg(col + j);
        int c1 = __ldg(col + j + 1);
        int c2 = __ldg(col + j + 2);
        int c3 = __ldg(col + j + 3);
        float2 v0 = base[(size_t)c0 * 32 + lane];
        float2 v1 = base[(size_t)c1 * 32 + lane];
        float2 v2 = base[(size_t)c2 * 32 + lane];
        float2 v3 = base[(size_t)c3 * 32 + lane];
        acc.x  += v0.x; acc.y  += v0.y;
        acc2.x += v1.x; acc2.y += v1.y;
        acc.x  += v2.x; acc.y  += v2.y;
        acc2.x += v3.x; acc2.y += v3.y;
    }
    for (; j < end; j++) {
        int c0 = __ldg(col + j);
        float2 v0 = base[(size_t)c0 * 32 + lane];
        acc.x += v0.x; acc.y += v0.y;
    }
    acc.x += acc2.x; acc.y += acc2.y;

    float2 b = reinterpret_cast<const float2*>(bias)[lane];
    float2 o;
    o.x = fmaxf(acc.x + b.x, 0.f);
    o.y = fmaxf(acc.y + b.y, 0.f);
    reinterpret_cast<float2*>(out)[(size_t)node * 32 + lane] = o;
}

// Fused-partials scan removed in favor of R3's dedicated kernel? No — R3 used
// a dedicated scan_partials launch; keep the R4 fused scan_add (measured fine
// at 4.6us and saves one launch; it was present in the 282us... it was NOT.
// R3 had scan_partials. But the fused variant was in R4-R7 and is semantically
// identical with one fewer launch; retained here as part of the CSR chain.

// ---------------------------------------------------------------------------
// Launch: single stream, R3 structure, memset replaces zero_cnt. 10 launches.
// ---------------------------------------------------------------------------
extern "C" void kernel_launch(void* const* d_in, const int* in_sizes, int n_in,
                              void* d_out, int out_size)
{
    const float* in_feat = (const float*)d_in[0];
    const float* W1 = (const float*)d_in[1];
    const float* b1 = (const float*)d_in[2];
    const float* W2 = (const float*)d_in[3];
    const float* b2 = (const float*)d_in[4];
    const float* W3 = (const float*)d_in[5];
    const float* b3 = (const float*)d_in[6];
    const int*   src = (const int*)d_in[7];
    const int*   dst = (const int*)d_in[8];
    float* out = (float*)d_out;

    float *y, *h;
    int *row_ptr, *cursor, *cnt, *col, *partials;
    cudaGetSymbolAddress((void**)&y, g_y);
    cudaGetSymbolAddress((void**)&h, g_h);
    cudaGetSymbolAddress((void**)&row_ptr, g_row_ptr);
    cudaGetSymbolAddress((void**)&cursor, g_cursor);
    cudaGetSymbolAddress((void**)&cnt, g_cnt);
    cudaGetSymbolAddress((void**)&col, g_col);
    cudaGetSymbolAddress((void**)&partials, g_partials);

    const int smem128 = (64 * (D + 4) + D * (128 + 4)) * (int)sizeof(float);
    const int smem64  = (64 * (D + 4) + D * (64 + 4))  * (int)sizeof(float);
    cudaFuncSetAttribute(gemm_kernel<128>,
                         cudaFuncAttributeMaxDynamicSharedMemorySize, smem128);
    cudaFuncSetAttribute(gemm_kernel<64>,
                         cudaFuncAttributeMaxDynamicSharedMemorySize, smem64);

    const int edge4_blocks = (N_EDGES / 4 + 255) / 256;
    const int gemm_blocks  = (N_NODES + 63) / 64;
    const int agg_blocks   = (N_NODES * 32 + 255) / 256;

    // ---- CSR build ----
    cudaMemsetAsync(cnt, 0, N_NODES * sizeof(int), 0);
    hist_kernel<<<edge4_blocks, 256>>>(dst, cnt);
    scan_block_kernel<<<SCAN_NBLK, SCAN_B>>>(cnt, row_ptr, partials);
    scan_add_kernel<<<SCAN_NBLK, SCAN_B>>>(row_ptr, cursor, partials);
    fill_kernel<<<edge4_blocks, 256>>>(src, dst, cursor, col);

    // ---- Layer 1: y = in_feat @ W1 ; h = relu(y + Ay + b1) ----
    gemm_kernel<128><<<gemm_blocks, 128, smem128>>>(in_feat, W1, y);
    aggregate128_kernel<<<agg_blocks, 256>>>(y, row_ptr, col, b1, h);

    // ---- Layer 2: y = h @ W2 ; h = relu(y + Ay + b2) ----
    gemm_kernel<128><<<gemm_blocks, 128, smem128>>>(h, W2, y);
    aggregate128_kernel<<<agg_blocks, 256>>>(y, row_ptr, col, b2, h);

    // ---- Layer 3: y = h @ W3 (64) ; out = relu(y + Ay + b3) ----
    gemm_kernel<64><<<gemm_blocks, 128, smem64>>>(h, W3, y);
    aggregate64_kernel<<<agg_blocks, 256>>>(y, row_ptr, col, b3, out);
}

// round 9
// speedup vs baseline: 1.3412x; 1.0830x over previous
#include <cuda_runtime.h>
#include <cstdint>

#define N_NODES 50000
#define N_EDGES 800000
#define D 128
#define NCLS 64
#define SCAN_B 1024
#define SCAN_NBLK ((N_NODES + SCAN_B - 1) / SCAN_B)   // 49

// ---------------------------------------------------------------------------
// Device-global scratch
// ---------------------------------------------------------------------------
__device__ __align__(16) float g_y[N_NODES * D];
__device__ __align__(16) float g_h[N_NODES * D];
__device__ int g_row_ptr[N_NODES + 1];
__device__ int g_cursor[N_NODES];
__device__ int g_cnt[N_NODES];
__device__ int g_col[N_EDGES];
__device__ int g_partials[SCAN_NBLK];

// ---------------------------------------------------------------------------
// CSR kernels
// ---------------------------------------------------------------------------
__global__ void __launch_bounds__(256) hist_kernel(
    const int* __restrict__ dst, int* __restrict__ cnt)
{
    int base = (blockIdx.x * blockDim.x + threadIdx.x) * 4;
    if (base + 3 < N_EDGES) {
        int4 d4 = *reinterpret_cast<const int4*>(dst + base);
        atomicAdd(cnt + d4.x, 1);
        atomicAdd(cnt + d4.y, 1);
        atomicAdd(cnt + d4.z, 1);
        atomicAdd(cnt + d4.w, 1);
    } else {
        for (int e = base; e < N_EDGES; e++) atomicAdd(cnt + dst[e], 1);
    }
}

__global__ void __launch_bounds__(SCAN_B) scan_block_kernel(
    const int* __restrict__ cnt, int* __restrict__ row_ptr, int* __restrict__ partials)
{
    __shared__ int wsum[32];
    int i = blockIdx.x * SCAN_B + threadIdx.x;
    int lane = threadIdx.x & 31;
    int wid  = threadIdx.x >> 5;

    int v = (i < N_NODES) ? cnt[i] : 0;
    int x = v;
    #pragma unroll
    for (int off = 1; off < 32; off <<= 1) {
        int t = __shfl_up_sync(0xffffffffu, x, off);
        if (lane >= off) x += t;
    }
    if (lane == 31) wsum[wid] = x;
    __syncthreads();
    if (wid == 0) {
        int w = wsum[lane];
        #pragma unroll
        for (int off = 1; off < 32; off <<= 1) {
            int t = __shfl_up_sync(0xffffffffu, w, off);
            if (lane >= off) w += t;
        }
        wsum[lane] = w;
    }
    __syncthreads();

    int excl = x - v + (wid ? wsum[wid - 1] : 0);
    if (i < N_NODES) row_ptr[i] = excl;
    if (threadIdx.x == SCAN_B - 1) partials[blockIdx.x] = excl + v;
}

__global__ void __launch_bounds__(SCAN_B) scan_add_kernel(
    int* __restrict__ row_ptr, int* __restrict__ cursor, const int* __restrict__ partials)
{
    __shared__ int sp[SCAN_NBLK];
    if (threadIdx.x < SCAN_NBLK) sp[threadIdx.x] = partials[threadIdx.x];
    __syncthreads();
    if (threadIdx.x == 0) {
        int run = 0;
        #pragma unroll
        for (int k = 0; k < SCAN_NBLK; k++) { int t = sp[k]; sp[k] = run; run += t; }
    }
    __syncthreads();

    int i = blockIdx.x * SCAN_B + threadIdx.x;
    if (i < N_NODES) {
        int r = row_ptr[i] + sp[blockIdx.x];
        row_ptr[i] = r;
        cursor[i]  = r;
    }
    if (i == 0) row_ptr[N_NODES] = N_EDGES;
}

__global__ void __launch_bounds__(256) fill_kernel(
    const int* __restrict__ src, const int* __restrict__ dst,
    int* __restrict__ cursor, int* __restrict__ col)
{
    int base = (blockIdx.x * blockDim.x + threadIdx.x) * 4;
    if (base + 3 < N_EDGES) {
        int4 d4 = *reinterpret_cast<const int4*>(dst + base);
        int4 s4 = *reinterpret_cast<const int4*>(src + base);
        int p0 = atomicAdd(cursor + d4.x, 1);
        int p1 = atomicAdd(cursor + d4.y, 1);
        int p2 = atomicAdd(cursor + d4.z, 1);
        int p3 = atomicAdd(cursor + d4.w, 1);
        col[p0] = s4.x; col[p1] = s4.y; col[p2] = s4.z; col[p3] = s4.w;
    } else {
        for (int e = base; e < N_EDGES; e++) {
            int pos = atomicAdd(cursor + dst[e], 1);
            col[pos] = src[e];
        }
    }
}

// ---------------------------------------------------------------------------
// f32x2 GEMM, K-split into two 64-wide chunks so smem = 51KB -> 4 blocks/SM
// (vs 101KB -> 2 blocks/SM). Same FLOPs, same total smem traffic, 2x the
// warps per SMSP for latency hiding.
// y[n,j] = sum_k A[n,k] * W[j,k].  BM=64 rows/block, 128 threads, RPT=8 rows.
// ---------------------------------------------------------------------------
template <int NOUT>
__global__ void __launch_bounds__(128) gemm_kernel(
    const float* __restrict__ A, const float* __restrict__ W, float* __restrict__ y)
{
    constexpr int BM  = 64;
    constexpr int KC  = 64;              // K chunk
    constexpr int TX  = NOUT / 8;        // 16 or 8
    constexpr int TY  = 128 / TX;        // 8 or 16
    constexpr int RPT = BM / TY;         // 8 or 4
    constexpr int SXS = KC + 4;          // 68
    constexpr int SWS = NOUT + 4;        // 132 or 68

    extern __shared__ float smem[];
    float* sX = smem;                    // [BM][SXS]
    float* sW = smem + BM * SXS;         // [KC][SWS]  (W chunk, transposed)

    const int tid  = threadIdx.x;
    const int row0 = blockIdx.x * BM;

    const int tx = tid % TX;
    const int ty = tid / TX;
    const int cbase = tx * 8;
    const int rbase = ty * RPT;

    unsigned long long acc[RPT][4];
    #pragma unroll
    for (int r = 0; r < RPT; r++)
        #pragma unroll
        for (int c = 0; c < 4; c++) acc[r][c] = 0ULL;

    #pragma unroll
    for (int kc = 0; kc < D; kc += KC) {
        // X tile chunk: [BM][KC], coalesced float4 loads
        #pragma unroll
        for (int i = tid; i < BM * (KC / 4); i += 128) {
            int r  = i >> 4;             // KC/4 == 16
            int c4 = i & 15;
            int gr = row0 + r;
            float4 v = make_float4(0.f, 0.f, 0.f, 0.f);
            if (gr < N_NODES)
                v = *reinterpret_cast<const float4*>(A + (size_t)gr * D + kc + c4 * 4);
            reinterpret_cast<float4*>(sX + r * SXS)[c4] = v;
        }
        // W chunk: rows n, cols [kc, kc+KC), transposed into sW[k][n]
        #pragma unroll
        for (int i = tid; i < NOUT * (KC / 4); i += 128) {
            int n  = i >> 4;
            int k4 = i & 15;
            float4 v = *reinterpret_cast<const float4*>(W + (size_t)n * D + kc + k4 * 4);
            sW[(k4 * 4 + 0) * SWS + n] = v.x;
            sW[(k4 * 4 + 1) * SWS + n] = v.y;
            sW[(k4 * 4 + 2) * SWS + n] = v.z;
            sW[(k4 * 4 + 3) * SWS + n] = v.w;
        }
        __syncthreads();

        #pragma unroll 4
        for (int k = 0; k < KC; k++) {
            const ulonglong2* bp = reinterpret_cast<const ulonglong2*>(sW + k * SWS + cbase);
            ulonglong2 bA = bp[0];
            ulonglong2 bB = bp[1];
            #pragma unroll
            for (int r = 0; r < RPT; r++) {
                float a = sX[(rbase + r) * SXS + k];
                unsigned long long a2;
                asm("mov.b64 %0, {%1, %1};" : "=l"(a2) : "f"(a));
                asm("fma.rn.f32x2 %0, %1, %2, %0;" : "+l"(acc[r][0]) : "l"(a2), "l"(bA.x));
                asm("fma.rn.f32x2 %0, %1, %2, %0;" : "+l"(acc[r][1]) : "l"(a2), "l"(bA.y));
                asm("fma.rn.f32x2 %0, %1, %2, %0;" : "+l"(acc[r][2]) : "l"(a2), "l"(bB.x));
                asm("fma.rn.f32x2 %0, %1, %2, %0;" : "+l"(acc[r][3]) : "l"(a2), "l"(bB.y));
            }
        }
        __syncthreads();
    }

    #pragma unroll
    for (int r = 0; r < RPT; r++) {
        int row = row0 + rbase + r;
        if (row >= N_NODES) continue;
        float o[8];
        #pragma unroll
        for (int c = 0; c < 4; c++)
            asm("mov.b64 {%0, %1}, %2;" : "=f"(o[2*c]), "=f"(o[2*c+1]) : "l"(acc[r][c]));
        float4* dst4 = reinterpret_cast<float4*>(y + (size_t)row * NOUT + cbase);
        dst4[0] = make_float4(o[0], o[1], o[2], o[3]);
        dst4[1] = make_float4(o[4], o[5], o[6], o[7]);
    }
}

// ---------------------------------------------------------------------------
// CSR aggregation + bias + relu. One warp per node, 4 gathers in flight (R3).
// ---------------------------------------------------------------------------
__global__ void __launch_bounds__(256) aggregate128_kernel(
    const float* __restrict__ y, const int* __restrict__ row_ptr,
    const int* __restrict__ col, const float* __restrict__ bias,
    float* __restrict__ out)
{
    int node = (blockIdx.x * blockDim.x + threadIdx.x) >> 5;
    int lane = threadIdx.x & 31;
    if (node >= N_NODES) return;

    int beg = __ldg(row_ptr + node);
    int end = __ldg(row_ptr + node + 1);

    const float4* base = reinterpret_cast<const float4*>(y);
    float4 acc = base[(size_t)node * 32 + lane];
    float4 acc2 = make_float4(0.f, 0.f, 0.f, 0.f);

    int j = beg;
    for (; j + 3 < end; j += 4) {
        int c0 = __ldg(col + j);
        int c1 = __ldg(col + j + 1);
        int c2 = __ldg(col + j + 2);
        int c3 = __ldg(col + j + 3);
        float4 v0 = base[(size_t)c0 * 32 + lane];
        float4 v1 = base[(size_t)c1 * 32 + lane];
        float4 v2 = base[(size_t)c2 * 32 + lane];
        float4 v3 = base[(size_t)c3 * 32 + lane];
        acc.x  += v0.x; acc.y  += v0.y; acc.z  += v0.z; acc.w  += v0.w;
        acc2.x += v1.x; acc2.y += v1.y; acc2.z += v1.z; acc2.w += v1.w;
        acc.x  += v2.x; acc.y  += v2.y; acc.z  += v2.z; acc.w  += v2.w;
        acc2.x += v3.x; acc2.y += v3.y; acc2.z += v3.z; acc2.w += v3.w;
    }
    for (; j < end; j++) {
        int c0 = __ldg(col + j);
        float4 v0 = base[(size_t)c0 * 32 + lane];
        acc.x += v0.x; acc.y += v0.y; acc.z += v0.z; acc.w += v0.w;
    }
    acc.x += acc2.x; acc.y += acc2.y; acc.z += acc2.z; acc.w += acc2.w;

    float4 b = reinterpret_cast<const float4*>(bias)[lane];
    float4 o;
    o.x = fmaxf(acc.x + b.x, 0.f);
    o.y = fmaxf(acc.y + b.y, 0.f);
    o.z = fmaxf(acc.z + b.z, 0.f);
    o.w = fmaxf(acc.w + b.w, 0.f);
    reinterpret_cast<float4*>(out)[(size_t)node * 32 + lane] = o;
}

__global__ void __launch_bounds__(256) aggregate64_kernel(
    const float* __restrict__ y, const int* __restrict__ row_ptr,
    const int* __restrict__ col, const float* __restrict__ bias,
    float* __restrict__ out)
{
    int node = (blockIdx.x * blockDim.x + threadIdx.x) >> 5;
    int lane = threadIdx.x & 31;
    if (node >= N_NODES) return;

    int beg = __ldg(row_ptr + node);
    int end = __ldg(row_ptr + node + 1);

    const float2* base = reinterpret_cast<const float2*>(y);
    float2 acc = base[(size_t)node * 32 + lane];
    float2 acc2 = make_float2(0.f, 0.f);

    int j = beg;
    for (; j + 3 < end; j += 4) {
        int c0 = __ldg(col + j);
        int c1 = __ldg(col + j + 1);
        int c2 = __ldg(col + j + 2);
        int c3 = __ldg(col + j + 3);
        float2 v0 = base[(size_t)c0 * 32 + lane];
        float2 v1 = base[(size_t)c1 * 32 + lane];
        float2 v2 = base[(size_t)c2 * 32 + lane];
        float2 v3 = base[(size_t)c3 * 32 + lane];
        acc.x  += v0.x; acc.y  += v0.y;
        acc2.x += v1.x; acc2.y += v1.y;
        acc.x  += v2.x; acc.y  += v2.y;
        acc2.x += v3.x; acc2.y += v3.y;
    }
    for (; j < end; j++) {
        int c0 = __ldg(col + j);
        float2 v0 = base[(size_t)c0 * 32 + lane];
        acc.x += v0.x; acc.y += v0.y;
    }
    acc.x += acc2.x; acc.y += acc2.y;

    float2 b = reinterpret_cast<const float2*>(bias)[lane];
    float2 o;
    o.x = fmaxf(acc.x + b.x, 0.f);
    o.y = fmaxf(acc.y + b.y, 0.f);
    reinterpret_cast<float2*>(out)[(size_t)node * 32 + lane] = o;
}

// ---------------------------------------------------------------------------
// Launch: single stream. gemm1 moved to 4th launch slot (it is independent of
// fill) so the ncu capture (4th kernel) lands on the GEMM next round.
// ---------------------------------------------------------------------------
extern "C" void kernel_launch(void* const* d_in, const int* in_sizes, int n_in,
                              void* d_out, int out_size)
{
    const float* in_feat = (const float*)d_in[0];
    const float* W1 = (const float*)d_in[1];
    const float* b1 = (const float*)d_in[2];
    const float* W2 = (const float*)d_in[3];
    const float* b2 = (const float*)d_in[4];
    const float* W3 = (const float*)d_in[5];
    const float* b3 = (const float*)d_in[6];
    const int*   src = (const int*)d_in[7];
    const int*   dst = (const int*)d_in[8];
    float* out = (float*)d_out;

    float *y, *h;
    int *row_ptr, *cursor, *cnt, *col, *partials;
    cudaGetSymbolAddress((void**)&y, g_y);
    cudaGetSymbolAddress((void**)&h, g_h);
    cudaGetSymbolAddress((void**)&row_ptr, g_row_ptr);
    cudaGetSymbolAddress((void**)&cursor, g_cursor);
    cudaGetSymbolAddress((void**)&cnt, g_cnt);
    cudaGetSymbolAddress((void**)&col, g_col);
    cudaGetSymbolAddress((void**)&partials, g_partials);

    const int smem128 = (64 * (64 + 4) + 64 * (128 + 4)) * (int)sizeof(float);  // ~51KB
    const int smem64  = (64 * (64 + 4) + 64 * (64 + 4))  * (int)sizeof(float);  // ~35KB
    cudaFuncSetAttribute(gemm_kernel<128>,
                         cudaFuncAttributeMaxDynamicSharedMemorySize, smem128);
    cudaFuncSetAttribute(gemm_kernel<64>,
                         cudaFuncAttributeMaxDynamicSharedMemorySize, smem64);

    const int edge4_blocks = (N_EDGES / 4 + 255) / 256;
    const int gemm_blocks  = (N_NODES + 63) / 64;
    const int agg_blocks   = (N_NODES * 32 + 255) / 256;

    // ---- CSR phase 1 + layer-1 GEMM interleaved (all serial, one stream) ----
    cudaMemsetAsync(cnt, 0, N_NODES * sizeof(int), 0);
    hist_kernel<<<edge4_blocks, 256>>>(dst, cnt);                       // 1
    scan_block_kernel<<<SCAN_NBLK, SCAN_B>>>(cnt, row_ptr, partials);   // 2
    scan_add_kernel<<<SCAN_NBLK, SCAN_B>>>(row_ptr, cursor, partials);  // 3
    gemm_kernel<128><<<gemm_blocks, 128, smem128>>>(in_feat, W1, y);    // 4 <- ncu
    fill_kernel<<<edge4_blocks, 256>>>(src, dst, cursor, col);          // 5

    // ---- Layer 1 boundary: h = relu(y + Ay + b1) ----
    aggregate128_kernel<<<agg_blocks, 256>>>(y, row_ptr, col, b1, h);   // 6

    // ---- Layer 2: y = h @ W2 ; h = relu(y + Ay + b2) ----
    gemm_kernel<128><<<gemm_blocks, 128, smem128>>>(h, W2, y);          // 7
    aggregate128_kernel<<<agg_blocks, 256>>>(y, row_ptr, col, b2, h);   // 8

    // ---- Layer 3: y = h @ W3 (64) ; out = relu(y + Ay + b3) ----
    gemm_kernel<64><<<gemm_blocks, 128, smem64>>>(h, W3, y);            // 9
    aggregate64_kernel<<<agg_blocks, 256>>>(y, row_ptr, col, b3, out);  // 10
}